// round 10
// baseline (speedup 1.0000x reference)
#include <cuda_runtime.h>
#include <math.h>
#include <stdint.h>

#define B_  4
#define L_  2048
#define D_  2048
#define H_  16
#define HD  128
#define BH  (B_*H_)

// ---------------- device scratch (allocation-free rule: __device__ globals) ----
__device__ float g_q[(size_t)BH * L_ * HD];     // (B,H,L,d)
__device__ float g_k[(size_t)BH * L_ * HD];     // (B,H,L,d)
__device__ float g_v[(size_t)BH * L_ * HD];     // (B,H,L,d)
__device__ float g_att[(size_t)B_ * L_ * D_];   // (B,L,H,d)
__device__ float g_qsq[BH * L_];
__device__ float g_ksq[BH * L_];
__device__ float g_cos[L_ * 64];
__device__ float g_sin[L_ * 64];

// ---------------- mma.sync helpers ---------------------------------------------
__device__ __forceinline__ uint32_t f2tf32(float x) {
    uint32_t r;
    asm("cvt.rna.tf32.f32 %0, %1;" : "=r"(r) : "f"(x));
    return r;
}
__device__ __forceinline__ void mma_tf32(float (&d)[4], const uint32_t (&a)[4],
                                         uint32_t b0, uint32_t b1) {
    asm volatile(
        "mma.sync.aligned.m16n8k8.row.col.f32.tf32.tf32.f32 "
        "{%0,%1,%2,%3}, {%4,%5,%6,%7}, {%8,%9}, {%0,%1,%2,%3};"
        : "+f"(d[0]), "+f"(d[1]), "+f"(d[2]), "+f"(d[3])
        : "r"(a[0]), "r"(a[1]), "r"(a[2]), "r"(a[3]), "r"(b0), "r"(b1));
}

// ---------------- RoPE tables (double-precision truth) ------------------------
__global__ void rope_table_kernel() {
    int l = blockIdx.x;
    int i = threadIdx.x;                       // 0..63
    double invf = exp(((double)(-2 * i) / 128.0) * log(10000.0));
    double th = (double)l * invf;
    double s, c;
    sincos(th, &s, &c);
    g_cos[l * 64 + i] = (float)c;
    g_sin[l * 64 + i] = (float)s;
}

// ---------------- GEMM core (EXACT R8 revert — proven 6618us) -------------------
// 128x128 CTA tile, 256 threads, 8 warps in 4x2 grid, warp tile m32 x n64.
// Double-buffered BK=16, register-staged global prefetch, static smem only.
#define BM 128
#define BN 128
#define BK 16
#define SAP 132

__device__ __forceinline__ void sgemm_compute_mma(const float* __restrict__ A,
                                                  const float* __restrict__ W,
                                                  int K, int bm, int bn,
                                                  float (&acc)[2][8][4]) {
    __shared__ uint32_t As[2][BK][SAP];   // As[buf][k][row], tf32 bits
    __shared__ uint32_t Ws[2][BK][SAP];   // Ws[buf][k][col], tf32 bits
    const int tid  = threadIdx.x;
    const int warp = tid >> 5, lane = tid & 31;
    const int wm0 = (warp >> 1) * 32, wn0 = (warp & 1) * 64;
    const int lr = lane >> 2;
    const int lc = lane & 3;
    const int ldr = tid >> 2;              // 0..63
    const int ldc = (tid & 3) << 2;        // 0,4,8,12

#pragma unroll
    for (int mt = 0; mt < 2; mt++)
#pragma unroll
        for (int nt = 0; nt < 8; nt++)
#pragma unroll
            for (int i = 0; i < 4; i++) acc[mt][nt][i] = 0.f;

    float4 va[2], vw[2];
#pragma unroll
    for (int p = 0; p < 2; p++) {
        int r = ldr + p * 64;
        va[p] = *(const float4*)(A + (size_t)(bm + r) * K + ldc);
        vw[p] = *(const float4*)(W + (size_t)(bn + r) * K + ldc);
    }
#pragma unroll
    for (int p = 0; p < 2; p++) {
        int r = ldr + p * 64;
        As[0][ldc + 0][r] = f2tf32(va[p].x); As[0][ldc + 1][r] = f2tf32(va[p].y);
        As[0][ldc + 2][r] = f2tf32(va[p].z); As[0][ldc + 3][r] = f2tf32(va[p].w);
        Ws[0][ldc + 0][r] = f2tf32(vw[p].x); Ws[0][ldc + 1][r] = f2tf32(vw[p].y);
        Ws[0][ldc + 2][r] = f2tf32(vw[p].z); Ws[0][ldc + 3][r] = f2tf32(vw[p].w);
    }
    __syncthreads();

    const int nit = K / BK;
    for (int it = 0; it < nit; it++) {
        const int cur = it & 1;

        if (it + 1 < nit) {
            const int k0 = (it + 1) * BK;
#pragma unroll
            for (int p = 0; p < 2; p++) {
                int r = ldr + p * 64;
                va[p] = *(const float4*)(A + (size_t)(bm + r) * K + k0 + ldc);
                vw[p] = *(const float4*)(W + (size_t)(bn + r) * K + k0 + ldc);
            }
        }

        const uint32_t (*Ac)[SAP] = As[cur];
        const uint32_t (*Wc)[SAP] = Ws[cur];
#pragma unroll
        for (int ks = 0; ks < BK / 8; ks++) {
            const int kb = ks * 8;
            uint32_t a[2][4];
#pragma unroll
            for (int mt = 0; mt < 2; mt++) {
                const int r = wm0 + mt * 16 + lr;
                a[mt][0] = Ac[kb + lc][r];
                a[mt][1] = Ac[kb + lc][r + 8];
                a[mt][2] = Ac[kb + lc + 4][r];
                a[mt][3] = Ac[kb + lc + 4][r + 8];
            }
#pragma unroll
            for (int nt = 0; nt < 8; nt++) {
                const int n = wn0 + nt * 8 + lr;
                uint32_t b0 = Wc[kb + lc][n];
                uint32_t b1 = Wc[kb + lc + 4][n];
                mma_tf32(acc[0][nt], a[0], b0, b1);
                mma_tf32(acc[1][nt], a[1], b0, b1);
            }
        }

        if (it + 1 < nit) {
            const int nxt = 1 - cur;
#pragma unroll
            for (int p = 0; p < 2; p++) {
                int r = ldr + p * 64;
                As[nxt][ldc + 0][r] = f2tf32(va[p].x);
                As[nxt][ldc + 1][r] = f2tf32(va[p].y);
                As[nxt][ldc + 2][r] = f2tf32(va[p].z);
                As[nxt][ldc + 3][r] = f2tf32(va[p].w);
                Ws[nxt][ldc + 0][r] = f2tf32(vw[p].x);
                Ws[nxt][ldc + 1][r] = f2tf32(vw[p].y);
                Ws[nxt][ldc + 2][r] = f2tf32(vw[p].z);
                Ws[nxt][ldc + 3][r] = f2tf32(vw[p].w);
            }
        }
        __syncthreads();
    }
}

// QKV projection: y = x @ W^T, stored remapped to (B,H,L,d)
__global__ void __launch_bounds__(256, 2) sgemm_qkv_kernel(const float* __restrict__ x,
                                                           const float* __restrict__ Wq,
                                                           const float* __restrict__ Wk,
                                                           const float* __restrict__ Wv) {
    const int z = blockIdx.z;
    const float* W = (z == 0) ? Wq : (z == 1) ? Wk : Wv;
    float* dst = (z == 0) ? g_q : (z == 1) ? g_k : g_v;
    float acc[2][8][4];
    const int bm = blockIdx.y * BM, bn = blockIdx.x * BN;
    sgemm_compute_mma(x, W, D_, bm, bn, acc);

    const int warp = threadIdx.x >> 5, lane = threadIdx.x & 31;
    const int wm0 = (warp >> 1) * 32, wn0 = (warp & 1) * 64;
    const int lr = lane >> 2, lc = lane & 3;
    const int h = bn >> 7;
#pragma unroll
    for (int mt = 0; mt < 2; mt++) {
        const int mlo = bm + wm0 + mt * 16 + lr;
#pragma unroll
        for (int nt = 0; nt < 8; nt++) {
            const int jj = wn0 + nt * 8 + 2 * lc;
#pragma unroll
            for (int half = 0; half < 2; half++) {
                const int m = mlo + half * 8;
                const int bb = m >> 11, l = m & 2047;
                float* p = dst + (((size_t)(bb * H_ + h) * L_ + l) * HD + jj);
                *(float2*)p = make_float2(acc[mt][nt][half * 2],
                                          acc[mt][nt][half * 2 + 1]);
            }
        }
    }
}

// Output projection: out = att @ Wo^T (plain row-major store)
__global__ void __launch_bounds__(256, 2) sgemm_out_kernel(const float* __restrict__ Wo,
                                                           float* __restrict__ C) {
    float acc[2][8][4];
    const int bm = blockIdx.y * BM, bn = blockIdx.x * BN;
    sgemm_compute_mma(g_att, Wo, D_, bm, bn, acc);

    const int warp = threadIdx.x >> 5, lane = threadIdx.x & 31;
    const int wm0 = (warp >> 1) * 32, wn0 = (warp & 1) * 64;
    const int lr = lane >> 2, lc = lane & 3;
#pragma unroll
    for (int mt = 0; mt < 2; mt++) {
        const int mlo = bm + wm0 + mt * 16 + lr;
#pragma unroll
        for (int nt = 0; nt < 8; nt++) {
            const int n0 = bn + wn0 + nt * 8 + 2 * lc;
#pragma unroll
            for (int half = 0; half < 2; half++) {
                const size_t m = mlo + half * 8;
                *(float2*)(C + m * D_ + n0) = make_float2(acc[mt][nt][half * 2],
                                                          acc[mt][nt][half * 2 + 1]);
            }
        }
    }
}

// ---------------- RoPE + sigmoid + row sum-of-squares --------------------------
__global__ void rope_kernel() {
    const int l = blockIdx.x, bh = blockIdx.y, j = threadIdx.x;
    const size_t base = ((size_t)bh * L_ + l) * HD;
    const float c = g_cos[l * 64 + (j & 63)];
    const float s = g_sin[l * 64 + (j & 63)];

    __shared__ float qr[128], kr[128];
    float qv = g_q[base + j], kv = g_k[base + j];
    qr[j] = qv; kr[j] = kv;
    __syncthreads();
    float qpart = (j < 64) ? -qr[j + 64] : qr[j - 64];
    float kpart = (j < 64) ? -kr[j + 64] : kr[j - 64];
    float qo = qv * c + qpart * s;
    float ko = kv * c + kpart * s;
    float qt = 1.f / (1.f + expf(-qo));
    float kt = 1.f / (1.f + expf(-ko));
    g_q[base + j] = qt;
    g_k[base + j] = kt;

    float q2 = qt * qt, k2 = kt * kt;
#pragma unroll
    for (int o = 16; o; o >>= 1) {
        q2 += __shfl_xor_sync(0xffffffffu, q2, o);
        k2 += __shfl_xor_sync(0xffffffffu, k2, o);
    }
    __shared__ float rq[4], rk[4];
    if ((j & 31) == 0) { rq[j >> 5] = q2; rk[j >> 5] = k2; }
    __syncthreads();
    if (j == 0) g_qsq[(size_t)bh * L_ + l] = rq[0] + rq[1] + rq[2] + rq[3];
    if (j == 1) g_ksq[(size_t)bh * L_ + l] = rk[0] + rk[1] + rk[2] + rk[3];
}

// ---------------- causal flash attention (fp32, 512 threads) --------------------
// Same tiles/smem/math as the proven R1 kernel; 16 warps instead of 8 so FFMA
// issue slots survive LDS/MUFU/barrier stalls. Each thread: 2 rows x 8 S-cols,
// O = 2 rows x 16 cols.
#define QS_STR 132
#define KS_STR 68
#define VS_STR 128
#define PS_STR 68
#define FLASH_SMEM ((128*QS_STR + 128*KS_STR + 64*VS_STR + 128*PS_STR + 128 + 64) * 4)
#define FTH 512

__global__ void __launch_bounds__(FTH) flash_kernel(const float* __restrict__ tau_p) {
    extern __shared__ float sm[];
    float* Qs  = sm;                    // [128][132] transposed: Qs[kk][r]
    float* Ks  = Qs + 128 * QS_STR;     // [128][68]  transposed: Ks[kk][c]
    float* Vs  = Ks + 128 * KS_STR;     // [64][128]  natural
    float* Ps  = Vs + 64 * VS_STR;      // [128][68]  natural
    float* sqs = Ps + 128 * PS_STR;     // [128]
    float* sks = sqs + 128;             // [64]

    const int qi = blockIdx.x;
    const int bh = blockIdx.y;
    const int b = bh >> 4, h = bh & 15;
    const int tid = threadIdx.x;
    const int lane = tid & 31, warp = tid >> 5;      // warp 0..15
    const int tx = tid & 7, ty = tid >> 3;           // ty 0..63

    float tr = tau_p[0];
    float tau = log1pf(expf(tr));
    tau = fminf(fmaxf(tau, 0.1f), 10.f);
    const float inv_tau = 1.f / tau;

    const size_t hbase = (size_t)bh * L_ * HD;
    const float* Qg = g_q + hbase + (size_t)qi * 128 * HD;

    // transposed-store loader indices (2-way conflict pattern, 16 warps)
    const int rl  = (warp >> 3) * 8 + (lane >> 2);   // 0..15
    const int c4l = ((warp & 7) << 2) + (lane & 3);  // 0..31

    // load Q tile transposed
#pragma unroll
    for (int rep = 0; rep < 8; rep++) {
        int r = rep * 16 + rl;
        float4 v = *(const float4*)(Qg + (size_t)r * HD + c4l * 4);
        Qs[(c4l * 4 + 0) * QS_STR + r] = v.x;
        Qs[(c4l * 4 + 1) * QS_STR + r] = v.y;
        Qs[(c4l * 4 + 2) * QS_STR + r] = v.z;
        Qs[(c4l * 4 + 3) * QS_STR + r] = v.w;
    }
    if (tid < 128) sqs[tid] = g_qsq[(size_t)bh * L_ + qi * 128 + tid];

    float m_i[2], l_i[2], O[2][16];
#pragma unroll
    for (int i = 0; i < 2; i++) {
        m_i[i] = -INFINITY; l_i[i] = 0.f;
#pragma unroll
        for (int cc = 0; cc < 16; cc++) O[i][cc] = 0.f;
    }

    const int ntk = 2 * qi + 2;
    for (int kt = 0; kt < ntk; kt++) {
        const int j0 = kt * 64;
        __syncthreads();

        // K tile transposed: 64 rows
#pragma unroll
        for (int rep = 0; rep < 4; rep++) {
            int r = rep * 16 + rl;
            float4 v = *(const float4*)(g_k + hbase + (size_t)(j0 + r) * HD + c4l * 4);
            Ks[(c4l * 4 + 0) * KS_STR + r] = v.x;
            Ks[(c4l * 4 + 1) * KS_STR + r] = v.y;
            Ks[(c4l * 4 + 2) * KS_STR + r] = v.z;
            Ks[(c4l * 4 + 3) * KS_STR + r] = v.w;
        }
        // V tile natural
        {
            const float* Vg = g_v + hbase + (size_t)j0 * HD;
#pragma unroll
            for (int rep = 0; rep < 4; rep++) {
                int idx = rep * FTH + tid;
                int k = idx >> 5, c4 = idx & 31;
                *(float4*)&Vs[k * VS_STR + c4 * 4] =
                    *(const float4*)(Vg + (size_t)k * HD + c4 * 4);
            }
        }
        if (tid < 64) sks[tid] = g_ksq[(size_t)bh * L_ + j0 + tid];
        __syncthreads();

        // S = Qt . Kt^T  (rows ty*2+{0,1}, cols tx*8..)
        float s[2][8];
#pragma unroll
        for (int i = 0; i < 2; i++)
#pragma unroll
            for (int j = 0; j < 8; j++) s[i][j] = 0.f;

#pragma unroll 8
        for (int kk = 0; kk < 128; kk++) {
            float2 qa  = *(const float2*)&Qs[kk * QS_STR + ty * 2];
            float4 kb0 = *(const float4*)&Ks[kk * KS_STR + tx * 8];
            float4 kb1 = *(const float4*)&Ks[kk * KS_STR + tx * 8 + 4];
            float bb[8] = {kb0.x, kb0.y, kb0.z, kb0.w, kb1.x, kb1.y, kb1.z, kb1.w};
#pragma unroll
            for (int j = 0; j < 8; j++) {
                s[0][j] = fmaf(qa.x, bb[j], s[0][j]);
                s[1][j] = fmaf(qa.y, bb[j], s[1][j]);
            }
        }

        // score transform + online softmax
#pragma unroll
        for (int i = 0; i < 2; i++) {
            const int gq_ = qi * 128 + ty * 2 + i;
            const float qs = sqs[ty * 2 + i];
            float rm = -INFINITY;
#pragma unroll
            for (int j = 0; j < 8; j++) {
                int gk = j0 + tx * 8 + j;
                float sc = (2.f * s[i][j] - qs - sks[tx * 8 + j]) * inv_tau;
                sc = (gk > gq_) ? -INFINITY : sc;
                s[i][j] = sc;
                rm = fmaxf(rm, sc);
            }
            rm = fmaxf(rm, __shfl_xor_sync(0xffffffffu, rm, 1));
            rm = fmaxf(rm, __shfl_xor_sync(0xffffffffu, rm, 2));
            rm = fmaxf(rm, __shfl_xor_sync(0xffffffffu, rm, 4));
            float mnew = fmaxf(m_i[i], rm);
            float scale = __expf(m_i[i] - mnew);
            float rs = 0.f;
#pragma unroll
            for (int j = 0; j < 8; j++) {
                float p = __expf(s[i][j] - mnew);
                s[i][j] = p; rs += p;
            }
            rs += __shfl_xor_sync(0xffffffffu, rs, 1);
            rs += __shfl_xor_sync(0xffffffffu, rs, 2);
            rs += __shfl_xor_sync(0xffffffffu, rs, 4);
            l_i[i] = l_i[i] * scale + rs;
            m_i[i] = mnew;
#pragma unroll
            for (int cc = 0; cc < 16; cc++) O[i][cc] *= scale;
            *(float4*)&Ps[(ty * 2 + i) * PS_STR + tx * 8] =
                make_float4(s[i][0], s[i][1], s[i][2], s[i][3]);
            *(float4*)&Ps[(ty * 2 + i) * PS_STR + tx * 8 + 4] =
                make_float4(s[i][4], s[i][5], s[i][6], s[i][7]);
        }
        __syncthreads();

        // O += P . V
#pragma unroll 4
        for (int k = 0; k < 64; k++) {
            float4 v0 = *(const float4*)&Vs[k * VS_STR + tx * 16];
            float4 v1 = *(const float4*)&Vs[k * VS_STR + tx * 16 + 4];
            float4 v2 = *(const float4*)&Vs[k * VS_STR + tx * 16 + 8];
            float4 v3 = *(const float4*)&Vs[k * VS_STR + tx * 16 + 12];
            float vv[16] = {v0.x, v0.y, v0.z, v0.w, v1.x, v1.y, v1.z, v1.w,
                            v2.x, v2.y, v2.z, v2.w, v3.x, v3.y, v3.z, v3.w};
            float p0 = Ps[(ty * 2 + 0) * PS_STR + k];
            float p1 = Ps[(ty * 2 + 1) * PS_STR + k];
#pragma unroll
            for (int cc = 0; cc < 16; cc++) {
                O[0][cc] = fmaf(p0, vv[cc], O[0][cc]);
                O[1][cc] = fmaf(p1, vv[cc], O[1][cc]);
            }
        }
    }

    // normalize + store to (B, L, H, d)
#pragma unroll
    for (int i = 0; i < 2; i++) {
        float invl = 1.f / l_i[i];
        int gq_ = qi * 128 + ty * 2 + i;
        size_t off = (((size_t)b * L_ + gq_) * H_ + h) * HD + tx * 16;
        *(float4*)&g_att[off]      = make_float4(O[i][0] * invl,  O[i][1] * invl,
                                                 O[i][2] * invl,  O[i][3] * invl);
        *(float4*)&g_att[off + 4]  = make_float4(O[i][4] * invl,  O[i][5] * invl,
                                                 O[i][6] * invl,  O[i][7] * invl);
        *(float4*)&g_att[off + 8]  = make_float4(O[i][8] * invl,  O[i][9] * invl,
                                                 O[i][10] * invl, O[i][11] * invl);
        *(float4*)&g_att[off + 12] = make_float4(O[i][12] * invl, O[i][13] * invl,
                                                 O[i][14] * invl, O[i][15] * invl);
    }
}

// ---------------- launch --------------------------------------------------------
extern "C" void kernel_launch(void* const* d_in, const int* in_sizes, int n_in,
                              void* d_out, int out_size) {
    const float* x   = (const float*)d_in[0];
    const float* Wq  = (const float*)d_in[1];
    const float* Wk  = (const float*)d_in[2];
    const float* Wv  = (const float*)d_in[3];
    const float* Wo  = (const float*)d_in[4];
    const float* tau = (const float*)d_in[5];
    float* out = (float*)d_out;

    cudaFuncSetAttribute(flash_kernel, cudaFuncAttributeMaxDynamicSharedMemorySize,
                         FLASH_SMEM);

    rope_table_kernel<<<L_, 64>>>();
    sgemm_qkv_kernel<<<dim3(D_ / BN, (B_ * L_) / BM, 3), 256>>>(x, Wq, Wk, Wv);
    rope_kernel<<<dim3(L_, BH), 128>>>();
    flash_kernel<<<dim3(L_ / 128, BH), FTH, FLASH_SMEM>>>(tau);
    sgemm_out_kernel<<<dim3(D_ / BN, (B_ * L_) / BM), 256>>>(Wo, out);
}

// round 11
// speedup vs baseline: 2.4582x; 2.4582x over previous
#include <cuda_runtime.h>
#include <math.h>
#include <stdint.h>

#define B_  4
#define L_  2048
#define D_  2048
#define H_  16
#define HD  128
#define BH  (B_*H_)

// ---------------- device scratch (allocation-free rule: __device__ globals) ----
__device__ float g_q[(size_t)BH * L_ * HD];     // (B,H,L,d)
__device__ float g_k[(size_t)BH * L_ * HD];     // (B,H,L,d)
__device__ float g_v[(size_t)BH * L_ * HD];     // (B,H,L,d)
__device__ float g_att[(size_t)B_ * L_ * D_];   // (B,L,H,d)
__device__ float g_qsq[BH * L_];
__device__ float g_ksq[BH * L_];
__device__ float g_cos[L_ * 64];
__device__ float g_sin[L_ * 64];

// ---------------- mma.sync helpers ---------------------------------------------
__device__ __forceinline__ uint32_t f2tf32(float x) {
    uint32_t r;
    asm("cvt.rna.tf32.f32 %0, %1;" : "=r"(r) : "f"(x));
    return r;
}
__device__ __forceinline__ void mma_tf32(float (&d)[4], const uint32_t (&a)[4],
                                         uint32_t b0, uint32_t b1) {
    asm volatile(
        "mma.sync.aligned.m16n8k8.row.col.f32.tf32.tf32.f32 "
        "{%0,%1,%2,%3}, {%4,%5,%6,%7}, {%8,%9}, {%0,%1,%2,%3};"
        : "+f"(d[0]), "+f"(d[1]), "+f"(d[2]), "+f"(d[3])
        : "r"(a[0]), "r"(a[1]), "r"(a[2]), "r"(a[3]), "r"(b0), "r"(b1));
}

// ---------------- RoPE tables (double-precision truth) ------------------------
__global__ void rope_table_kernel() {
    int l = blockIdx.x;
    int i = threadIdx.x;                       // 0..63
    double invf = exp(((double)(-2 * i) / 128.0) * log(10000.0));
    double th = (double)l * invf;
    double s, c;
    sincos(th, &s, &c);
    g_cos[l * 64 + i] = (float)c;
    g_sin[l * 64 + i] = (float)s;
}

// ---------------- GEMM core (EXACT R8 — proven 6618us) --------------------------
#define BM 128
#define BN 128
#define BK 16
#define SAP 132

__device__ __forceinline__ void sgemm_compute_mma(const float* __restrict__ A,
                                                  const float* __restrict__ W,
                                                  int K, int bm, int bn,
                                                  float (&acc)[2][8][4]) {
    __shared__ uint32_t As[2][BK][SAP];
    __shared__ uint32_t Ws[2][BK][SAP];
    const int tid  = threadIdx.x;
    const int warp = tid >> 5, lane = tid & 31;
    const int wm0 = (warp >> 1) * 32, wn0 = (warp & 1) * 64;
    const int lr = lane >> 2;
    const int lc = lane & 3;
    const int ldr = tid >> 2;
    const int ldc = (tid & 3) << 2;

#pragma unroll
    for (int mt = 0; mt < 2; mt++)
#pragma unroll
        for (int nt = 0; nt < 8; nt++)
#pragma unroll
            for (int i = 0; i < 4; i++) acc[mt][nt][i] = 0.f;

    float4 va[2], vw[2];
#pragma unroll
    for (int p = 0; p < 2; p++) {
        int r = ldr + p * 64;
        va[p] = *(const float4*)(A + (size_t)(bm + r) * K + ldc);
        vw[p] = *(const float4*)(W + (size_t)(bn + r) * K + ldc);
    }
#pragma unroll
    for (int p = 0; p < 2; p++) {
        int r = ldr + p * 64;
        As[0][ldc + 0][r] = f2tf32(va[p].x); As[0][ldc + 1][r] = f2tf32(va[p].y);
        As[0][ldc + 2][r] = f2tf32(va[p].z); As[0][ldc + 3][r] = f2tf32(va[p].w);
        Ws[0][ldc + 0][r] = f2tf32(vw[p].x); Ws[0][ldc + 1][r] = f2tf32(vw[p].y);
        Ws[0][ldc + 2][r] = f2tf32(vw[p].z); Ws[0][ldc + 3][r] = f2tf32(vw[p].w);
    }
    __syncthreads();

    const int nit = K / BK;
    for (int it = 0; it < nit; it++) {
        const int cur = it & 1;

        if (it + 1 < nit) {
            const int k0 = (it + 1) * BK;
#pragma unroll
            for (int p = 0; p < 2; p++) {
                int r = ldr + p * 64;
                va[p] = *(const float4*)(A + (size_t)(bm + r) * K + k0 + ldc);
                vw[p] = *(const float4*)(W + (size_t)(bn + r) * K + k0 + ldc);
            }
        }

        const uint32_t (*Ac)[SAP] = As[cur];
        const uint32_t (*Wc)[SAP] = Ws[cur];
#pragma unroll
        for (int ks = 0; ks < BK / 8; ks++) {
            const int kb = ks * 8;
            uint32_t a[2][4];
#pragma unroll
            for (int mt = 0; mt < 2; mt++) {
                const int r = wm0 + mt * 16 + lr;
                a[mt][0] = Ac[kb + lc][r];
                a[mt][1] = Ac[kb + lc][r + 8];
                a[mt][2] = Ac[kb + lc + 4][r];
                a[mt][3] = Ac[kb + lc + 4][r + 8];
            }
#pragma unroll
            for (int nt = 0; nt < 8; nt++) {
                const int n = wn0 + nt * 8 + lr;
                uint32_t b0 = Wc[kb + lc][n];
                uint32_t b1 = Wc[kb + lc + 4][n];
                mma_tf32(acc[0][nt], a[0], b0, b1);
                mma_tf32(acc[1][nt], a[1], b0, b1);
            }
        }

        if (it + 1 < nit) {
            const int nxt = 1 - cur;
#pragma unroll
            for (int p = 0; p < 2; p++) {
                int r = ldr + p * 64;
                As[nxt][ldc + 0][r] = f2tf32(va[p].x);
                As[nxt][ldc + 1][r] = f2tf32(va[p].y);
                As[nxt][ldc + 2][r] = f2tf32(va[p].z);
                As[nxt][ldc + 3][r] = f2tf32(va[p].w);
                Ws[nxt][ldc + 0][r] = f2tf32(vw[p].x);
                Ws[nxt][ldc + 1][r] = f2tf32(vw[p].y);
                Ws[nxt][ldc + 2][r] = f2tf32(vw[p].z);
                Ws[nxt][ldc + 3][r] = f2tf32(vw[p].w);
            }
        }
        __syncthreads();
    }
}

__global__ void __launch_bounds__(256, 2) sgemm_qkv_kernel(const float* __restrict__ x,
                                                           const float* __restrict__ Wq,
                                                           const float* __restrict__ Wk,
                                                           const float* __restrict__ Wv) {
    const int z = blockIdx.z;
    const float* W = (z == 0) ? Wq : (z == 1) ? Wk : Wv;
    float* dst = (z == 0) ? g_q : (z == 1) ? g_k : g_v;
    float acc[2][8][4];
    const int bm = blockIdx.y * BM, bn = blockIdx.x * BN;
    sgemm_compute_mma(x, W, D_, bm, bn, acc);

    const int warp = threadIdx.x >> 5, lane = threadIdx.x & 31;
    const int wm0 = (warp >> 1) * 32, wn0 = (warp & 1) * 64;
    const int lr = lane >> 2, lc = lane & 3;
    const int h = bn >> 7;
#pragma unroll
    for (int mt = 0; mt < 2; mt++) {
        const int mlo = bm + wm0 + mt * 16 + lr;
#pragma unroll
        for (int nt = 0; nt < 8; nt++) {
            const int jj = wn0 + nt * 8 + 2 * lc;
#pragma unroll
            for (int half = 0; half < 2; half++) {
                const int m = mlo + half * 8;
                const int bb = m >> 11, l = m & 2047;
                float* p = dst + (((size_t)(bb * H_ + h) * L_ + l) * HD + jj);
                *(float2*)p = make_float2(acc[mt][nt][half * 2],
                                          acc[mt][nt][half * 2 + 1]);
            }
        }
    }
}

__global__ void __launch_bounds__(256, 2) sgemm_out_kernel(const float* __restrict__ Wo,
                                                           float* __restrict__ C) {
    float acc[2][8][4];
    const int bm = blockIdx.y * BM, bn = blockIdx.x * BN;
    sgemm_compute_mma(g_att, Wo, D_, bm, bn, acc);

    const int warp = threadIdx.x >> 5, lane = threadIdx.x & 31;
    const int wm0 = (warp >> 1) * 32, wn0 = (warp & 1) * 64;
    const int lr = lane >> 2, lc = lane & 3;
#pragma unroll
    for (int mt = 0; mt < 2; mt++) {
        const int mlo = bm + wm0 + mt * 16 + lr;
#pragma unroll
        for (int nt = 0; nt < 8; nt++) {
            const int n0 = bn + wn0 + nt * 8 + 2 * lc;
#pragma unroll
            for (int half = 0; half < 2; half++) {
                const size_t m = mlo + half * 8;
                *(float2*)(C + m * D_ + n0) = make_float2(acc[mt][nt][half * 2],
                                                          acc[mt][nt][half * 2 + 1]);
            }
        }
    }
}

// ---------------- RoPE + sigmoid + row sum-of-squares --------------------------
__global__ void rope_kernel() {
    const int l = blockIdx.x, bh = blockIdx.y, j = threadIdx.x;
    const size_t base = ((size_t)bh * L_ + l) * HD;
    const float c = g_cos[l * 64 + (j & 63)];
    const float s = g_sin[l * 64 + (j & 63)];

    __shared__ float qr[128], kr[128];
    float qv = g_q[base + j], kv = g_k[base + j];
    qr[j] = qv; kr[j] = kv;
    __syncthreads();
    float qpart = (j < 64) ? -qr[j + 64] : qr[j - 64];
    float kpart = (j < 64) ? -kr[j + 64] : kr[j - 64];
    float qo = qv * c + qpart * s;
    float ko = kv * c + kpart * s;
    float qt = 1.f / (1.f + expf(-qo));
    float kt = 1.f / (1.f + expf(-ko));
    g_q[base + j] = qt;
    g_k[base + j] = kt;

    float q2 = qt * qt, k2 = kt * kt;
#pragma unroll
    for (int o = 16; o; o >>= 1) {
        q2 += __shfl_xor_sync(0xffffffffu, q2, o);
        k2 += __shfl_xor_sync(0xffffffffu, k2, o);
    }
    __shared__ float rq[4], rk[4];
    if ((j & 31) == 0) { rq[j >> 5] = q2; rk[j >> 5] = k2; }
    __syncthreads();
    if (j == 0) g_qsq[(size_t)bh * L_ + l] = rq[0] + rq[1] + rq[2] + rq[3];
    if (j == 1) g_ksq[(size_t)bh * L_ + l] = rk[0] + rk[1] + rk[2] + rk[3];
}

// ---------------- causal flash attention via mma.sync tf32 ----------------------
// 256 threads = 8 warps, each warp owns a 16-row band of the 128-row Q tile.
// K-tile = 64 keys. S = QK^T in split-tf32 (3 MMAs, ~2^-21 accurate); PV with
// single-tf32 P and V (zero-mean rounding, ~1.5e-4 each in the norm).
// Smem: Qt fp32 [128][132] transposed; Kp (hi,lo) uint2 [64][132]; Vs tf32 bits
// [64][132] natural; Ps tf32 bits [128][68]; sqs/sks. Total 204,544 B.
#define FQ_STR 132
#define FK_STR 132
#define FV_STR 132
#define FP_STR 68
#define FLASH_WORDS (128*FQ_STR + 64*FK_STR*2 + 64*FV_STR + 128*FP_STR + 128 + 64)
#define FLASH_SMEM (FLASH_WORDS * 4)

__global__ void __launch_bounds__(256) flash_kernel(const float* __restrict__ tau_p) {
    extern __shared__ float sm[];
    float*     Qt = sm;                                        // [128][132] fp32
    uint2*     Kp = (uint2*)(sm + 128 * FQ_STR);               // [64][132] (hi,lo)
    uint32_t*  Vs = (uint32_t*)(sm + 128 * FQ_STR + 64 * FK_STR * 2); // [64][132]
    float*     Ps = sm + 128 * FQ_STR + 64 * FK_STR * 2 + 64 * FV_STR; // [128][68]
    float*     sqs = Ps + 128 * FP_STR;                        // [128]
    float*     sks = sqs + 128;                                // [64]

    const int qi = blockIdx.x;
    const int bh = blockIdx.y;
    const int b = bh >> 4, h = bh & 15;
    const int tid = threadIdx.x;
    const int lane = tid & 31, warp = tid >> 5;
    const int lr = lane >> 2, lc = lane & 3;
    const int r0 = warp * 16 + lr;           // first row of this thread's pair

    float tr = tau_p[0];
    float tau = log1pf(expf(tr));
    tau = fminf(fmaxf(tau, 0.1f), 10.f);
    const float inv_tau = 1.f / tau;

    const size_t hbase = (size_t)bh * L_ * HD;
    const float* Qg = g_q + hbase + (size_t)qi * 128 * HD;

    // load Q tile transposed (R1-proven pattern)
    {
        const int rl = lane >> 2;
        const int c4 = (warp << 2) + (lane & 3);
#pragma unroll
        for (int rep = 0; rep < 16; rep++) {
            int r = rep * 8 + rl;
            float4 v = *(const float4*)(Qg + (size_t)r * HD + c4 * 4);
            Qt[(c4 * 4 + 0) * FQ_STR + r] = v.x;
            Qt[(c4 * 4 + 1) * FQ_STR + r] = v.y;
            Qt[(c4 * 4 + 2) * FQ_STR + r] = v.z;
            Qt[(c4 * 4 + 3) * FQ_STR + r] = v.w;
        }
    }
    if (tid < 128) sqs[tid] = g_qsq[(size_t)bh * L_ + qi * 128 + tid];

    float m_i[2] = {-INFINITY, -INFINITY};
    float l_i[2] = {0.f, 0.f};
    float O[16][4];
#pragma unroll
    for (int nf = 0; nf < 16; nf++)
#pragma unroll
        for (int i = 0; i < 4; i++) O[nf][i] = 0.f;

    const int ntk = 2 * qi + 2;
    for (int kt = 0; kt < ntk; kt++) {
        const int j0 = kt * 64;
        __syncthreads();   // prior PV reads of Kp/Vs done before overwrite

        // load K tile, split into (hi,lo) tf32 pairs
#pragma unroll
        for (int t = 0; t < 8; t++) {
            int idx = tid + t * 256;
            int r = idx >> 5, c4 = (idx & 31) << 2;
            float4 v = *(const float4*)(g_k + hbase + (size_t)(j0 + r) * HD + c4);
            uint32_t hx = f2tf32(v.x), hy = f2tf32(v.y);
            uint32_t hz = f2tf32(v.z), hw = f2tf32(v.w);
            uint32_t lx = f2tf32(v.x - __uint_as_float(hx));
            uint32_t ly = f2tf32(v.y - __uint_as_float(hy));
            uint32_t lz = f2tf32(v.z - __uint_as_float(hz));
            uint32_t lw = f2tf32(v.w - __uint_as_float(hw));
            uint4* dst = (uint4*)(Kp + r * FK_STR + c4);
            dst[0] = make_uint4(hx, lx, hy, ly);
            dst[1] = make_uint4(hz, lz, hw, lw);
        }
        // load V tile natural, convert to tf32 bits
#pragma unroll
        for (int t = 0; t < 8; t++) {
            int idx = tid + t * 256;
            int k = idx >> 5, c4 = (idx & 31) << 2;
            float4 v = *(const float4*)(g_v + hbase + (size_t)(j0 + k) * HD + c4);
            *(uint4*)(Vs + k * FV_STR + c4) =
                make_uint4(f2tf32(v.x), f2tf32(v.y), f2tf32(v.z), f2tf32(v.w));
        }
        if (tid < 64) sks[tid] = g_ksq[(size_t)bh * L_ + j0 + tid];
        __syncthreads();

        // ---- S = Q K^T (split-tf32: hi*hi + hi*lo + lo*hi) ----
        float sacc[8][4];
#pragma unroll
        for (int nf = 0; nf < 8; nf++)
#pragma unroll
            for (int i = 0; i < 4; i++) sacc[nf][i] = 0.f;

#pragma unroll
        for (int ks = 0; ks < 16; ks++) {
            const int kb = ks * 8;
            float x0 = Qt[(kb + lc) * FQ_STR + r0];
            float x1 = Qt[(kb + lc) * FQ_STR + r0 + 8];
            float x2 = Qt[(kb + lc + 4) * FQ_STR + r0];
            float x3 = Qt[(kb + lc + 4) * FQ_STR + r0 + 8];
            uint32_t ah[4], al[4];
            ah[0] = f2tf32(x0); al[0] = f2tf32(x0 - __uint_as_float(ah[0]));
            ah[1] = f2tf32(x1); al[1] = f2tf32(x1 - __uint_as_float(ah[1]));
            ah[2] = f2tf32(x2); al[2] = f2tf32(x2 - __uint_as_float(ah[2]));
            ah[3] = f2tf32(x3); al[3] = f2tf32(x3 - __uint_as_float(ah[3]));
#pragma unroll
            for (int nf = 0; nf < 8; nf++) {
                const int n = nf * 8 + lr;
                uint2 p0 = Kp[n * FK_STR + kb + lc];
                uint2 p1 = Kp[n * FK_STR + kb + lc + 4];
                mma_tf32(sacc[nf], ah, p0.x, p1.x);   // hi*hi
                mma_tf32(sacc[nf], ah, p0.y, p1.y);   // hi*lo
                mma_tf32(sacc[nf], al, p0.x, p1.x);   // lo*hi
            }
        }

        // ---- score transform + online softmax (C-frag layout) ----
        const float sq0 = sqs[r0], sq1 = sqs[r0 + 8];
        const int gq0 = qi * 128 + r0, gq1 = gq0 + 8;
        float rm[2] = {-INFINITY, -INFINITY};
#pragma unroll
        for (int nf = 0; nf < 8; nf++) {
            const int cb = j0 + nf * 8 + 2 * lc;
            const float kq0 = sks[nf * 8 + 2 * lc];
            const float kq1 = sks[nf * 8 + 2 * lc + 1];
            float v00 = (2.f * sacc[nf][0] - sq0 - kq0) * inv_tau;
            float v01 = (2.f * sacc[nf][1] - sq0 - kq1) * inv_tau;
            float v10 = (2.f * sacc[nf][2] - sq1 - kq0) * inv_tau;
            float v11 = (2.f * sacc[nf][3] - sq1 - kq1) * inv_tau;
            v00 = (cb > gq0) ? -INFINITY : v00;
            v01 = (cb + 1 > gq0) ? -INFINITY : v01;
            v10 = (cb > gq1) ? -INFINITY : v10;
            v11 = (cb + 1 > gq1) ? -INFINITY : v11;
            sacc[nf][0] = v00; sacc[nf][1] = v01;
            sacc[nf][2] = v10; sacc[nf][3] = v11;
            rm[0] = fmaxf(rm[0], fmaxf(v00, v01));
            rm[1] = fmaxf(rm[1], fmaxf(v10, v11));
        }
#pragma unroll
        for (int i = 0; i < 2; i++) {
            rm[i] = fmaxf(rm[i], __shfl_xor_sync(0xffffffffu, rm[i], 1));
            rm[i] = fmaxf(rm[i], __shfl_xor_sync(0xffffffffu, rm[i], 2));
        }
        float mnew[2], scale[2], rs[2] = {0.f, 0.f};
#pragma unroll
        for (int i = 0; i < 2; i++) {
            mnew[i] = fmaxf(m_i[i], rm[i]);
            scale[i] = __expf(m_i[i] - mnew[i]);
        }
#pragma unroll
        for (int nf = 0; nf < 8; nf++) {
            float p00 = __expf(sacc[nf][0] - mnew[0]);
            float p01 = __expf(sacc[nf][1] - mnew[0]);
            float p10 = __expf(sacc[nf][2] - mnew[1]);
            float p11 = __expf(sacc[nf][3] - mnew[1]);
            rs[0] += p00 + p01;
            rs[1] += p10 + p11;
            // store P as tf32 bits (same-warp consumption)
            const int cc = nf * 8 + 2 * lc;
            *(uint2*)((uint32_t*)Ps + r0 * FP_STR + cc) =
                make_uint2(f2tf32(p00), f2tf32(p01));
            *(uint2*)((uint32_t*)Ps + (r0 + 8) * FP_STR + cc) =
                make_uint2(f2tf32(p10), f2tf32(p11));
        }
#pragma unroll
        for (int i = 0; i < 2; i++) {
            rs[i] += __shfl_xor_sync(0xffffffffu, rs[i], 1);
            rs[i] += __shfl_xor_sync(0xffffffffu, rs[i], 2);
            l_i[i] = l_i[i] * scale[i] + rs[i];
            m_i[i] = mnew[i];
        }
#pragma unroll
        for (int nf = 0; nf < 16; nf++) {
            O[nf][0] *= scale[0]; O[nf][1] *= scale[0];
            O[nf][2] *= scale[1]; O[nf][3] *= scale[1];
        }
        __syncwarp();   // P rows of this warp written by its own lanes

        // ---- O += P V (single-tf32 P and V) ----
        const uint32_t* Pu = (const uint32_t*)Ps;
#pragma unroll
        for (int ks = 0; ks < 8; ks++) {
            const int kb = ks * 8;
            uint32_t pa[4];
            pa[0] = Pu[r0 * FP_STR + kb + lc];
            pa[1] = Pu[(r0 + 8) * FP_STR + kb + lc];
            pa[2] = Pu[r0 * FP_STR + kb + lc + 4];
            pa[3] = Pu[(r0 + 8) * FP_STR + kb + lc + 4];
#pragma unroll
            for (int nf = 0; nf < 16; nf++) {
                const int n = nf * 8 + lr;
                uint32_t b0 = Vs[(kb + lc) * FV_STR + n];
                uint32_t b1 = Vs[(kb + lc + 4) * FV_STR + n];
                mma_tf32(O[nf], pa, b0, b1);
            }
        }
    }

    // normalize + store to (B, L, H, d)
    const float il0 = 1.f / l_i[0], il1 = 1.f / l_i[1];
    const int gq0 = qi * 128 + r0;
#pragma unroll
    for (int nf = 0; nf < 16; nf++) {
        const int col = nf * 8 + 2 * lc;
        size_t off0 = (((size_t)b * L_ + gq0) * H_ + h) * HD + col;
        size_t off1 = (((size_t)b * L_ + gq0 + 8) * H_ + h) * HD + col;
        *(float2*)&g_att[off0] = make_float2(O[nf][0] * il0, O[nf][1] * il0);
        *(float2*)&g_att[off1] = make_float2(O[nf][2] * il1, O[nf][3] * il1);
    }
}

// ---------------- launch --------------------------------------------------------
extern "C" void kernel_launch(void* const* d_in, const int* in_sizes, int n_in,
                              void* d_out, int out_size) {
    const float* x   = (const float*)d_in[0];
    const float* Wq  = (const float*)d_in[1];
    const float* Wk  = (const float*)d_in[2];
    const float* Wv  = (const float*)d_in[3];
    const float* Wo  = (const float*)d_in[4];
    const float* tau = (const float*)d_in[5];
    float* out = (float*)d_out;

    cudaFuncSetAttribute(flash_kernel, cudaFuncAttributeMaxDynamicSharedMemorySize,
                         FLASH_SMEM);

    rope_table_kernel<<<L_, 64>>>();
    sgemm_qkv_kernel<<<dim3(D_ / BN, (B_ * L_) / BM, 3), 256>>>(x, Wq, Wk, Wv);
    rope_kernel<<<dim3(L_, BH), 128>>>();
    flash_kernel<<<dim3(L_ / 128, BH), 256, FLASH_SMEM>>>(tau);
    sgemm_out_kernel<<<dim3(D_ / BN, (B_ * L_) / BM), 256>>>(Wo, out);
}

// round 12
// speedup vs baseline: 2.6459x; 1.0763x over previous
#include <cuda_runtime.h>
#include <cuda_bf16.h>
#include <math.h>
#include <stdint.h>

#define B_  4
#define L_  2048
#define D_  2048
#define H_  16
#define HD  128
#define BH  (B_*H_)

// ---------------- device scratch (allocation-free rule: __device__ globals) ----
__device__ float g_q[(size_t)BH * L_ * HD];     // (B,H,L,d)
__device__ float g_k[(size_t)BH * L_ * HD];     // (B,H,L,d)
__device__ float g_v[(size_t)BH * L_ * HD];     // (B,H,L,d)
__device__ float g_att[(size_t)B_ * L_ * D_];   // (B,L,H,d)
__device__ float g_qsq[BH * L_];
__device__ float g_ksq[BH * L_];
__device__ float g_cos[L_ * 64];
__device__ float g_sin[L_ * 64];

// ---------------- mma helpers ----------------------------------------------------
__device__ __forceinline__ uint32_t f2tf32(float x) {
    uint32_t r;
    asm("cvt.rna.tf32.f32 %0, %1;" : "=r"(r) : "f"(x));
    return r;
}
__device__ __forceinline__ void mma_tf32(float (&d)[4], const uint32_t (&a)[4],
                                         uint32_t b0, uint32_t b1) {
    asm volatile(
        "mma.sync.aligned.m16n8k8.row.col.f32.tf32.tf32.f32 "
        "{%0,%1,%2,%3}, {%4,%5,%6,%7}, {%8,%9}, {%0,%1,%2,%3};"
        : "+f"(d[0]), "+f"(d[1]), "+f"(d[2]), "+f"(d[3])
        : "r"(a[0]), "r"(a[1]), "r"(a[2]), "r"(a[3]), "r"(b0), "r"(b1));
}
__device__ __forceinline__ void mma_bf16(float (&d)[4], const uint32_t (&a)[4],
                                         uint32_t b0, uint32_t b1) {
    asm volatile(
        "mma.sync.aligned.m16n8k16.row.col.f32.bf16.bf16.f32 "
        "{%0,%1,%2,%3}, {%4,%5,%6,%7}, {%8,%9}, {%0,%1,%2,%3};"
        : "+f"(d[0]), "+f"(d[1]), "+f"(d[2]), "+f"(d[3])
        : "r"(a[0]), "r"(a[1]), "r"(a[2]), "r"(a[3]), "r"(b0), "r"(b1));
}
// pack two floats into bf16x2 word: lo half = first arg, hi half = second
__device__ __forceinline__ uint32_t bfpack(float lo, float hi) {
    uint32_t d;
    asm("cvt.rn.bf16x2.f32 %0, %1, %2;" : "=r"(d) : "f"(hi), "f"(lo));
    return d;
}
__device__ __forceinline__ float bfhi(float f) {
    return __bfloat162float(__float2bfloat16(f));
}

// ---------------- RoPE tables (double-precision truth) ------------------------
__global__ void rope_table_kernel() {
    int l = blockIdx.x;
    int i = threadIdx.x;                       // 0..63
    double invf = exp(((double)(-2 * i) / 128.0) * log(10000.0));
    double th = (double)l * invf;
    double s, c;
    sincos(th, &s, &c);
    g_cos[l * 64 + i] = (float)c;
    g_sin[l * 64 + i] = (float)s;
}

// ---------------- GEMM core (EXACT R8 — proven) ---------------------------------
#define BM 128
#define BN 128
#define BK 16
#define SAP 132

__device__ __forceinline__ void sgemm_compute_mma(const float* __restrict__ A,
                                                  const float* __restrict__ W,
                                                  int K, int bm, int bn,
                                                  float (&acc)[2][8][4]) {
    __shared__ uint32_t As[2][BK][SAP];
    __shared__ uint32_t Ws[2][BK][SAP];
    const int tid  = threadIdx.x;
    const int warp = tid >> 5, lane = tid & 31;
    const int wm0 = (warp >> 1) * 32, wn0 = (warp & 1) * 64;
    const int lr = lane >> 2;
    const int lc = lane & 3;
    const int ldr = tid >> 2;
    const int ldc = (tid & 3) << 2;

#pragma unroll
    for (int mt = 0; mt < 2; mt++)
#pragma unroll
        for (int nt = 0; nt < 8; nt++)
#pragma unroll
            for (int i = 0; i < 4; i++) acc[mt][nt][i] = 0.f;

    float4 va[2], vw[2];
#pragma unroll
    for (int p = 0; p < 2; p++) {
        int r = ldr + p * 64;
        va[p] = *(const float4*)(A + (size_t)(bm + r) * K + ldc);
        vw[p] = *(const float4*)(W + (size_t)(bn + r) * K + ldc);
    }
#pragma unroll
    for (int p = 0; p < 2; p++) {
        int r = ldr + p * 64;
        As[0][ldc + 0][r] = f2tf32(va[p].x); As[0][ldc + 1][r] = f2tf32(va[p].y);
        As[0][ldc + 2][r] = f2tf32(va[p].z); As[0][ldc + 3][r] = f2tf32(va[p].w);
        Ws[0][ldc + 0][r] = f2tf32(vw[p].x); Ws[0][ldc + 1][r] = f2tf32(vw[p].y);
        Ws[0][ldc + 2][r] = f2tf32(vw[p].z); Ws[0][ldc + 3][r] = f2tf32(vw[p].w);
    }
    __syncthreads();

    const int nit = K / BK;
    for (int it = 0; it < nit; it++) {
        const int cur = it & 1;

        if (it + 1 < nit) {
            const int k0 = (it + 1) * BK;
#pragma unroll
            for (int p = 0; p < 2; p++) {
                int r = ldr + p * 64;
                va[p] = *(const float4*)(A + (size_t)(bm + r) * K + k0 + ldc);
                vw[p] = *(const float4*)(W + (size_t)(bn + r) * K + k0 + ldc);
            }
        }

        const uint32_t (*Ac)[SAP] = As[cur];
        const uint32_t (*Wc)[SAP] = Ws[cur];
#pragma unroll
        for (int ks = 0; ks < BK / 8; ks++) {
            const int kb = ks * 8;
            uint32_t a[2][4];
#pragma unroll
            for (int mt = 0; mt < 2; mt++) {
                const int r = wm0 + mt * 16 + lr;
                a[mt][0] = Ac[kb + lc][r];
                a[mt][1] = Ac[kb + lc][r + 8];
                a[mt][2] = Ac[kb + lc + 4][r];
                a[mt][3] = Ac[kb + lc + 4][r + 8];
            }
#pragma unroll
            for (int nt = 0; nt < 8; nt++) {
                const int n = wn0 + nt * 8 + lr;
                uint32_t b0 = Wc[kb + lc][n];
                uint32_t b1 = Wc[kb + lc + 4][n];
                mma_tf32(acc[0][nt], a[0], b0, b1);
                mma_tf32(acc[1][nt], a[1], b0, b1);
            }
        }

        if (it + 1 < nit) {
            const int nxt = 1 - cur;
#pragma unroll
            for (int p = 0; p < 2; p++) {
                int r = ldr + p * 64;
                As[nxt][ldc + 0][r] = f2tf32(va[p].x);
                As[nxt][ldc + 1][r] = f2tf32(va[p].y);
                As[nxt][ldc + 2][r] = f2tf32(va[p].z);
                As[nxt][ldc + 3][r] = f2tf32(va[p].w);
                Ws[nxt][ldc + 0][r] = f2tf32(vw[p].x);
                Ws[nxt][ldc + 1][r] = f2tf32(vw[p].y);
                Ws[nxt][ldc + 2][r] = f2tf32(vw[p].z);
                Ws[nxt][ldc + 3][r] = f2tf32(vw[p].w);
            }
        }
        __syncthreads();
    }
}

__global__ void __launch_bounds__(256, 2) sgemm_qkv_kernel(const float* __restrict__ x,
                                                           const float* __restrict__ Wq,
                                                           const float* __restrict__ Wk,
                                                           const float* __restrict__ Wv) {
    const int z = blockIdx.z;
    const float* W = (z == 0) ? Wq : (z == 1) ? Wk : Wv;
    float* dst = (z == 0) ? g_q : (z == 1) ? g_k : g_v;
    float acc[2][8][4];
    const int bm = blockIdx.y * BM, bn = blockIdx.x * BN;
    sgemm_compute_mma(x, W, D_, bm, bn, acc);

    const int warp = threadIdx.x >> 5, lane = threadIdx.x & 31;
    const int wm0 = (warp >> 1) * 32, wn0 = (warp & 1) * 64;
    const int lr = lane >> 2, lc = lane & 3;
    const int h = bn >> 7;
#pragma unroll
    for (int mt = 0; mt < 2; mt++) {
        const int mlo = bm + wm0 + mt * 16 + lr;
#pragma unroll
        for (int nt = 0; nt < 8; nt++) {
            const int jj = wn0 + nt * 8 + 2 * lc;
#pragma unroll
            for (int half = 0; half < 2; half++) {
                const int m = mlo + half * 8;
                const int bb = m >> 11, l = m & 2047;
                float* p = dst + (((size_t)(bb * H_ + h) * L_ + l) * HD + jj);
                *(float2*)p = make_float2(acc[mt][nt][half * 2],
                                          acc[mt][nt][half * 2 + 1]);
            }
        }
    }
}

__global__ void __launch_bounds__(256, 2) sgemm_out_kernel(const float* __restrict__ Wo,
                                                           float* __restrict__ C) {
    float acc[2][8][4];
    const int bm = blockIdx.y * BM, bn = blockIdx.x * BN;
    sgemm_compute_mma(g_att, Wo, D_, bm, bn, acc);

    const int warp = threadIdx.x >> 5, lane = threadIdx.x & 31;
    const int wm0 = (warp >> 1) * 32, wn0 = (warp & 1) * 64;
    const int lr = lane >> 2, lc = lane & 3;
#pragma unroll
    for (int mt = 0; mt < 2; mt++) {
        const int mlo = bm + wm0 + mt * 16 + lr;
#pragma unroll
        for (int nt = 0; nt < 8; nt++) {
            const int n0 = bn + wn0 + nt * 8 + 2 * lc;
#pragma unroll
            for (int half = 0; half < 2; half++) {
                const size_t m = mlo + half * 8;
                *(float2*)(C + m * D_ + n0) = make_float2(acc[mt][nt][half * 2],
                                                          acc[mt][nt][half * 2 + 1]);
            }
        }
    }
}

// ---------------- RoPE + sigmoid + row sum-of-squares --------------------------
__global__ void rope_kernel() {
    const int l = blockIdx.x, bh = blockIdx.y, j = threadIdx.x;
    const size_t base = ((size_t)bh * L_ + l) * HD;
    const float c = g_cos[l * 64 + (j & 63)];
    const float s = g_sin[l * 64 + (j & 63)];

    __shared__ float qr[128], kr[128];
    float qv = g_q[base + j], kv = g_k[base + j];
    qr[j] = qv; kr[j] = kv;
    __syncthreads();
    float qpart = (j < 64) ? -qr[j + 64] : qr[j - 64];
    float kpart = (j < 64) ? -kr[j + 64] : kr[j - 64];
    float qo = qv * c + qpart * s;
    float ko = kv * c + kpart * s;
    float qt = 1.f / (1.f + expf(-qo));
    float kt = 1.f / (1.f + expf(-ko));
    g_q[base + j] = qt;
    g_k[base + j] = kt;

    float q2 = qt * qt, k2 = kt * kt;
#pragma unroll
    for (int o = 16; o; o >>= 1) {
        q2 += __shfl_xor_sync(0xffffffffu, q2, o);
        k2 += __shfl_xor_sync(0xffffffffu, k2, o);
    }
    __shared__ float rq[4], rk[4];
    if ((j & 31) == 0) { rq[j >> 5] = q2; rk[j >> 5] = k2; }
    __syncthreads();
    if (j == 0) g_qsq[(size_t)bh * L_ + l] = rq[0] + rq[1] + rq[2] + rq[3];
    if (j == 1) g_ksq[(size_t)bh * L_ + l] = rk[0] + rk[1] + rk[2] + rk[3];
}

// ---------------- causal flash attention: bf16-split S + tf32 PV -----------------
// 256 threads = 8 warps, warp = 16-row band. K-tile 64 keys.
// S = QK^T via m16n8k16 bf16 split (qh*kh + qh*kl + ql*kh): 3 MMA per k16,
// operands precomputed into packed bf16x2 smem planes with (lc,lc+4)-paired
// uint2 layout (LDS.64 fragments). PV: single-tf32 m16n8k8, V rows paired.
#define QPW 68            // u32 per Q-plane row (32 uint2 + 2 pad)
#define KPW 68            // u32 per K-plane row
#define VPW 264           // u32 per V pair-row (2*128 + 8 pad)
#define FP_STR 68
#define OFF_QH 0
#define OFF_QL (128*QPW)
#define OFF_KH (2*128*QPW)
#define OFF_KL (OFF_KH + 64*KPW)
#define OFF_VP (OFF_KL + 64*KPW)
#define OFF_PS (OFF_VP + 32*VPW)
#define OFF_SQS (OFF_PS + 128*FP_STR)
#define OFF_SKS (OFF_SQS + 128)
#define FLASH_SMEM ((OFF_SKS + 64) * 4)

__global__ void __launch_bounds__(256) flash_kernel(const float* __restrict__ tau_p) {
    extern __shared__ uint32_t smu[];
    float* sqs = (float*)(smu + OFF_SQS);
    float* sks = (float*)(smu + OFF_SKS);
    uint32_t* Pu = smu + OFF_PS;

    const int qi = blockIdx.x;
    const int bh = blockIdx.y;
    const int b = bh >> 4, h = bh & 15;
    const int tid = threadIdx.x;
    const int lane = tid & 31, warp = tid >> 5;
    const int lr = lane >> 2, lc = lane & 3;
    const int r0 = warp * 16 + lr;

    float tr = tau_p[0];
    float tau = log1pf(expf(tr));
    tau = fminf(fmaxf(tau, 0.1f), 10.f);
    const float inv_tau = 1.f / tau;

    const size_t hbase = (size_t)bh * L_ * HD;
    const float* Qg = g_q + hbase + (size_t)qi * 128 * HD;

    // ---- load Q once: split into bf16 hi/lo planes, packed (k even, k odd),
    //      pair-interleaved columns: entry[s*4+lc] = {word(kp=8s+lc), word(kp=8s+4+lc)}
#pragma unroll
    for (int t = 0; t < 16; t++) {
        int idx = tid + t * 256;
        int row = idx >> 5, c4 = idx & 31;
        float4 v = *(const float4*)(Qg + (size_t)row * HD + c4 * 4);
        float hx = bfhi(v.x), hy = bfhi(v.y), hz = bfhi(v.z), hw = bfhi(v.w);
        // kp a = 2*c4 (v.x,v.y), kp b = 2*c4+1 (v.z,v.w)
        int kpa = 2 * c4, kpb = kpa + 1;
        int sa = kpa >> 3, ja = kpa & 7;
        int ia = row * QPW + ((sa << 2) + (ja & 3)) * 2 + (ja >> 2);
        int sb = kpb >> 3, jb = kpb & 7;
        int ib = row * QPW + ((sb << 2) + (jb & 3)) * 2 + (jb >> 2);
        smu[OFF_QH + ia] = bfpack(hx, hy);
        smu[OFF_QL + ia] = bfpack(v.x - hx, v.y - hy);
        smu[OFF_QH + ib] = bfpack(hz, hw);
        smu[OFF_QL + ib] = bfpack(v.z - hz, v.w - hw);
    }
    if (tid < 128) sqs[tid] = g_qsq[(size_t)bh * L_ + qi * 128 + tid];

    float m_i[2] = {-INFINITY, -INFINITY};
    float l_i[2] = {0.f, 0.f};
    float O[16][4];
#pragma unroll
    for (int nf = 0; nf < 16; nf++)
#pragma unroll
        for (int i = 0; i < 4; i++) O[nf][i] = 0.f;

    const int ntk = 2 * qi + 2;
    for (int kt = 0; kt < ntk; kt++) {
        const int j0 = kt * 64;
        __syncthreads();   // prev S/PV reads done (also Q-store visibility, 1st iter)

        // ---- load K tile: split bf16 planes, same packing as Q (64 rows)
#pragma unroll
        for (int t = 0; t < 8; t++) {
            int idx = tid + t * 256;
            int row = idx >> 5, c4 = idx & 31;
            float4 v = *(const float4*)(g_k + hbase + (size_t)(j0 + row) * HD + c4 * 4);
            float hx = bfhi(v.x), hy = bfhi(v.y), hz = bfhi(v.z), hw = bfhi(v.w);
            int kpa = 2 * c4, kpb = kpa + 1;
            int sa = kpa >> 3, ja = kpa & 7;
            int ia = row * KPW + ((sa << 2) + (ja & 3)) * 2 + (ja >> 2);
            int sb = kpb >> 3, jb = kpb & 7;
            int ib = row * KPW + ((sb << 2) + (jb & 3)) * 2 + (jb >> 2);
            smu[OFF_KH + ia] = bfpack(hx, hy);
            smu[OFF_KL + ia] = bfpack(v.x - hx, v.y - hy);
            smu[OFF_KH + ib] = bfpack(hz, hw);
            smu[OFF_KL + ib] = bfpack(v.z - hz, v.w - hw);
        }
        // ---- load V tile: tf32 bits, rows paired (k, k+4) per ks8 group
#pragma unroll
        for (int t = 0; t < 8; t++) {
            int idx = tid + t * 256;
            int k = idx >> 5, c4 = idx & 31;
            float4 v = *(const float4*)(g_v + hbase + (size_t)(j0 + k) * HD + c4 * 4);
            int ks = k >> 3, j = k & 7;
            int pr = (ks << 2) + (j & 3), half = j >> 2;
            uint32_t base = OFF_VP + pr * VPW + (c4 * 4) * 2 + half;
            smu[base + 0] = f2tf32(v.x);
            smu[base + 2] = f2tf32(v.y);
            smu[base + 4] = f2tf32(v.z);
            smu[base + 6] = f2tf32(v.w);
        }
        if (tid < 64) sks[tid] = g_ksq[(size_t)bh * L_ + j0 + tid];
        __syncthreads();

        // ---- S = QK^T via bf16-split m16n8k16 (3 MMA per k16) ----
        float sacc[8][4];
#pragma unroll
        for (int nf = 0; nf < 8; nf++)
#pragma unroll
            for (int i = 0; i < 4; i++) sacc[nf][i] = 0.f;

#pragma unroll
        for (int s8 = 0; s8 < 8; s8++) {
            const int ci = ((s8 << 2) + lc) * 2;
            uint2 qh0 = *(const uint2*)(smu + OFF_QH + r0 * QPW + ci);
            uint2 qh1 = *(const uint2*)(smu + OFF_QH + (r0 + 8) * QPW + ci);
            uint2 ql0 = *(const uint2*)(smu + OFF_QL + r0 * QPW + ci);
            uint2 ql1 = *(const uint2*)(smu + OFF_QL + (r0 + 8) * QPW + ci);
            uint32_t ah[4] = {qh0.x, qh1.x, qh0.y, qh1.y};
            uint32_t al[4] = {ql0.x, ql1.x, ql0.y, ql1.y};
#pragma unroll
            for (int nf = 0; nf < 8; nf++) {
                const int n = nf * 8 + lr;
                uint2 bhp = *(const uint2*)(smu + OFF_KH + n * KPW + ci);
                uint2 blp = *(const uint2*)(smu + OFF_KL + n * KPW + ci);
                mma_bf16(sacc[nf], ah, bhp.x, bhp.y);
                mma_bf16(sacc[nf], ah, blp.x, blp.y);
                mma_bf16(sacc[nf], al, bhp.x, bhp.y);
            }
        }

        // ---- score transform + online softmax (C-frag layout) ----
        const float sq0 = sqs[r0], sq1 = sqs[r0 + 8];
        const int gq0 = qi * 128 + r0, gq1 = gq0 + 8;
        float rm[2] = {-INFINITY, -INFINITY};
#pragma unroll
        for (int nf = 0; nf < 8; nf++) {
            const int cb = j0 + nf * 8 + 2 * lc;
            const float kq0 = sks[nf * 8 + 2 * lc];
            const float kq1 = sks[nf * 8 + 2 * lc + 1];
            float v00 = (2.f * sacc[nf][0] - sq0 - kq0) * inv_tau;
            float v01 = (2.f * sacc[nf][1] - sq0 - kq1) * inv_tau;
            float v10 = (2.f * sacc[nf][2] - sq1 - kq0) * inv_tau;
            float v11 = (2.f * sacc[nf][3] - sq1 - kq1) * inv_tau;
            v00 = (cb > gq0) ? -INFINITY : v00;
            v01 = (cb + 1 > gq0) ? -INFINITY : v01;
            v10 = (cb > gq1) ? -INFINITY : v10;
            v11 = (cb + 1 > gq1) ? -INFINITY : v11;
            sacc[nf][0] = v00; sacc[nf][1] = v01;
            sacc[nf][2] = v10; sacc[nf][3] = v11;
            rm[0] = fmaxf(rm[0], fmaxf(v00, v01));
            rm[1] = fmaxf(rm[1], fmaxf(v10, v11));
        }
#pragma unroll
        for (int i = 0; i < 2; i++) {
            rm[i] = fmaxf(rm[i], __shfl_xor_sync(0xffffffffu, rm[i], 1));
            rm[i] = fmaxf(rm[i], __shfl_xor_sync(0xffffffffu, rm[i], 2));
        }
        float mnew[2], scale[2], rs[2] = {0.f, 0.f};
#pragma unroll
        for (int i = 0; i < 2; i++) {
            mnew[i] = fmaxf(m_i[i], rm[i]);
            scale[i] = __expf(m_i[i] - mnew[i]);
        }
#pragma unroll
        for (int nf = 0; nf < 8; nf++) {
            float p00 = __expf(sacc[nf][0] - mnew[0]);
            float p01 = __expf(sacc[nf][1] - mnew[0]);
            float p10 = __expf(sacc[nf][2] - mnew[1]);
            float p11 = __expf(sacc[nf][3] - mnew[1]);
            rs[0] += p00 + p01;
            rs[1] += p10 + p11;
            const int cc = nf * 8 + 2 * lc;
            *(uint2*)(Pu + r0 * FP_STR + cc) = make_uint2(f2tf32(p00), f2tf32(p01));
            *(uint2*)(Pu + (r0 + 8) * FP_STR + cc) = make_uint2(f2tf32(p10), f2tf32(p11));
        }
#pragma unroll
        for (int i = 0; i < 2; i++) {
            rs[i] += __shfl_xor_sync(0xffffffffu, rs[i], 1);
            rs[i] += __shfl_xor_sync(0xffffffffu, rs[i], 2);
            l_i[i] = l_i[i] * scale[i] + rs[i];
            m_i[i] = mnew[i];
        }
#pragma unroll
        for (int nf = 0; nf < 16; nf++) {
            O[nf][0] *= scale[0]; O[nf][1] *= scale[0];
            O[nf][2] *= scale[1]; O[nf][3] *= scale[1];
        }
        __syncwarp();   // this warp's P rows written by its own lanes

        // ---- O += P V (single-tf32, paired V rows -> LDS.64) ----
#pragma unroll
        for (int ks = 0; ks < 8; ks++) {
            const int kb = ks * 8;
            uint32_t pa[4];
            pa[0] = Pu[r0 * FP_STR + kb + lc];
            pa[1] = Pu[(r0 + 8) * FP_STR + kb + lc];
            pa[2] = Pu[r0 * FP_STR + kb + lc + 4];
            pa[3] = Pu[(r0 + 8) * FP_STR + kb + lc + 4];
            const uint32_t vbase = OFF_VP + ((ks << 2) + lc) * VPW;
#pragma unroll
            for (int nf = 0; nf < 16; nf++) {
                const int n = nf * 8 + lr;
                uint2 bv = *(const uint2*)(smu + vbase + 2 * n);
                mma_tf32(O[nf], pa, bv.x, bv.y);
            }
        }
    }

    // normalize + store to (B, L, H, d)
    const float il0 = 1.f / l_i[0], il1 = 1.f / l_i[1];
    const int gq0 = qi * 128 + r0;
#pragma unroll
    for (int nf = 0; nf < 16; nf++) {
        const int col = nf * 8 + 2 * lc;
        size_t off0 = (((size_t)b * L_ + gq0) * H_ + h) * HD + col;
        size_t off1 = (((size_t)b * L_ + gq0 + 8) * H_ + h) * HD + col;
        *(float2*)&g_att[off0] = make_float2(O[nf][0] * il0, O[nf][1] * il0);
        *(float2*)&g_att[off1] = make_float2(O[nf][2] * il1, O[nf][3] * il1);
    }
}

// ---------------- launch --------------------------------------------------------
extern "C" void kernel_launch(void* const* d_in, const int* in_sizes, int n_in,
                              void* d_out, int out_size) {
    const float* x   = (const float*)d_in[0];
    const float* Wq  = (const float*)d_in[1];
    const float* Wk  = (const float*)d_in[2];
    const float* Wv  = (const float*)d_in[3];
    const float* Wo  = (const float*)d_in[4];
    const float* tau = (const float*)d_in[5];
    float* out = (float*)d_out;

    cudaFuncSetAttribute(flash_kernel, cudaFuncAttributeMaxDynamicSharedMemorySize,
                         FLASH_SMEM);

    rope_table_kernel<<<L_, 64>>>();
    sgemm_qkv_kernel<<<dim3(D_ / BN, (B_ * L_) / BM, 3), 256>>>(x, Wq, Wk, Wv);
    rope_kernel<<<dim3(L_, BH), 128>>>();
    flash_kernel<<<dim3(L_ / 128, BH), 256, FLASH_SMEM>>>(tau);
    sgemm_out_kernel<<<dim3(D_ / BN, (B_ * L_) / BM), 256>>>(Wo, out);
}